// round 1
// baseline (speedup 1.0000x reference)
#include <cuda_runtime.h>
#include <cuda_bf16.h>
#include <math.h>

// Problem dims (fixed by the benchmark):
//   l_enc: [1024, 128, 256] fp32  -> N = 131072 rows of C = 256
//   g_enc: [1024, 256]      fp32  -> K = 1024
#define C_DIM   256
#define K_TOT   1024
#define N_ROWS  131072
#define INV_T   5.0f   // 1/T, T = 0.2

// Scratch: normalized + transposed operands ([c][n] / [c][k] layouts).
__device__ float d_lT[(size_t)C_DIM * N_ROWS];   // 134 MB
__device__ float d_gT[(size_t)C_DIM * K_TOT];    // 1 MB

// ---------------------------------------------------------------------------
// Zero the scalar output (d_out is poisoned by the harness).
// ---------------------------------------------------------------------------
__global__ void zero_out_kernel(float* out) {
    if (threadIdx.x == 0) out[0] = 0.0f;
}

// ---------------------------------------------------------------------------
// Normalize rows of src [nrows, 256] and write transposed dst [256][ldst].
// One block = 32 rows, 256 threads.
// ---------------------------------------------------------------------------
__global__ void norm_transpose_kernel(const float* __restrict__ src,
                                      float* __restrict__ dst,
                                      int ldst) {
    __shared__ float t[32][257];   // padded: conflict-free column reads
    __shared__ float rn[32];
    const int n0  = blockIdx.x * 32;
    const int tid = threadIdx.x;

    // Load 32 rows x 256 cols, coalesced float4 along C.
    for (int idx = tid; idx < 32 * 64; idx += 256) {
        const int r  = idx >> 6;
        const int c4 = idx & 63;
        const float4 v = ((const float4*)src)[(size_t)(n0 + r) * 64 + c4];
        t[r][c4 * 4 + 0] = v.x;
        t[r][c4 * 4 + 1] = v.y;
        t[r][c4 * 4 + 2] = v.z;
        t[r][c4 * 4 + 3] = v.w;
    }
    __syncthreads();

    // Row sum-of-squares: 8 threads per row, shfl-reduce within groups of 8.
    {
        const int r = tid >> 3;
        const int p = tid & 7;
        float s = 0.0f;
        #pragma unroll
        for (int c = 0; c < 32; c++) {
            const float x = t[r][p * 32 + c];
            s += x * x;
        }
        #pragma unroll
        for (int o = 4; o > 0; o >>= 1)
            s += __shfl_down_sync(0xffffffffu, s, o, 8);
        if (p == 0) rn[r] = rsqrtf(s);
    }
    __syncthreads();

    // Write transposed: dst[c][n0 + j] = t[j][c] * rn[j]; coalesced over j.
    for (int idx = tid; idx < C_DIM * 32; idx += 256) {
        const int c = idx >> 5;
        const int j = idx & 31;
        dst[(size_t)c * ldst + n0 + j] = t[j][c] * rn[j];
    }
}

// ---------------------------------------------------------------------------
// Main fused kernel:
//   per block: 64 rows (one shared positive index b = n0/128), sweep all
//   K=1024 in 16 tiles of 64, 4x4 register microtile per thread (256 thr).
//   Epilogue: rowsum of exp(cos/T); positive cos captured from its tile.
//   val_row = log(S - exp(cos_b/T)) - cos_b/T ; atomicAdd(mean contribution).
// ---------------------------------------------------------------------------
__global__ void contrastive_main_kernel(float* __restrict__ out) {
    extern __shared__ float sm[];
    float* sx   = sm;                      // [256][64] normalized l tile
    float* sg   = sm + C_DIM * 64;         // [256][64] normalized g tile
    float* spos = sg + C_DIM * 64;         // [64] positive cosines
    float* sred = spos + 64;               // [64][16] rowsum reduction

    const int tid = threadIdx.x;
    const int tx  = tid & 15;              // k-fragment group (16)
    const int ty  = tid >> 4;              // row-fragment group (16)
    const int n0  = blockIdx.x * 64;
    const int b   = n0 >> 7;               // shared positive graph index

    // Load this block's l tile [c][64] once (coalesced over j).
    for (int idx = tid; idx < C_DIM * 64; idx += 256) {
        const int c = idx >> 6;
        const int j = idx & 63;
        sx[c * 64 + j] = d_lT[(size_t)c * N_ROWS + n0 + j];
    }
    __syncthreads();

    float rs[4] = {0.0f, 0.0f, 0.0f, 0.0f};
    const int b_tile = b >> 6;
    const int b_col  = b & 63;

    for (int kt = 0; kt < K_TOT / 64; kt++) {
        // Load g tile [c][64] (1MB total -> L2 resident after first wave).
        for (int idx = tid; idx < C_DIM * 64; idx += 256) {
            const int c = idx >> 6;
            const int j = idx & 63;
            sg[c * 64 + j] = d_gT[(size_t)c * K_TOT + kt * 64 + j];
        }
        __syncthreads();

        float acc[4][4];
        #pragma unroll
        for (int i = 0; i < 4; i++)
            #pragma unroll
            for (int j = 0; j < 4; j++) acc[i][j] = 0.0f;

        #pragma unroll 8
        for (int c = 0; c < C_DIM; c++) {
            const float4 a4 = *(const float4*)&sx[c * 64 + ty * 4];
            const float4 b4 = *(const float4*)&sg[c * 64 + tx * 4];
            const float av[4] = {a4.x, a4.y, a4.z, a4.w};
            const float bv[4] = {b4.x, b4.y, b4.z, b4.w};
            #pragma unroll
            for (int i = 0; i < 4; i++)
                #pragma unroll
                for (int j = 0; j < 4; j++)
                    acc[i][j] += av[i] * bv[j];
        }

        // Capture positive cosines for this block's b (one thread column).
        if (kt == b_tile && tx == (b_col >> 2)) {
            const int j = b_col & 3;
            #pragma unroll
            for (int i = 0; i < 4; i++) spos[ty * 4 + i] = acc[i][j];
        }

        // Fold tile into per-row exp-sums.
        #pragma unroll
        for (int i = 0; i < 4; i++)
            #pragma unroll
            for (int j = 0; j < 4; j++)
                rs[i] += __expf(acc[i][j] * INV_T);

        __syncthreads();   // before overwriting sg
    }

    // Reduce rowsums across the 16 tx threads per row.
    #pragma unroll
    for (int i = 0; i < 4; i++)
        sred[(ty * 4 + i) * 16 + tx] = rs[i];
    __syncthreads();

    float v = 0.0f;
    if (tid < 64) {
        float S = 0.0f;
        #pragma unroll
        for (int t = 0; t < 16; t++) S += sred[tid * 16 + t];
        const float p = spos[tid] * INV_T;      // cos_b / T
        v = logf(S - __expf(p)) - p;            // per-row loss contribution
    }
    // Reduce v over first 64 threads (2 warps).
    #pragma unroll
    for (int o = 16; o > 0; o >>= 1)
        v += __shfl_down_sync(0xffffffffu, v, o);
    __syncthreads();   // sred reuse safety
    if (tid < 64 && (tid & 31) == 0) sred[tid >> 5] = v;
    __syncthreads();
    if (tid == 0)
        atomicAdd(out, (sred[0] + sred[1]) * (1.0f / (float)N_ROWS));
}

// ---------------------------------------------------------------------------
// Launch
// ---------------------------------------------------------------------------
extern "C" void kernel_launch(void* const* d_in, const int* in_sizes, int n_in,
                              void* d_out, int out_size) {
    const float* l_enc = (const float*)d_in[0];   // [1024,128,256]
    const float* g_enc = (const float*)d_in[1];   // [1024,256]
    float* out = (float*)d_out;

    float* lT = nullptr;
    float* gT = nullptr;
    cudaGetSymbolAddress((void**)&lT, d_lT);
    cudaGetSymbolAddress((void**)&gT, d_gT);

    const int smem_bytes = (C_DIM * 64 * 2 + 64 + 64 * 16) * (int)sizeof(float);
    cudaFuncSetAttribute(contrastive_main_kernel,
                         cudaFuncAttributeMaxDynamicSharedMemorySize,
                         smem_bytes);

    zero_out_kernel<<<1, 32>>>(out);
    norm_transpose_kernel<<<N_ROWS / 32, 256>>>(l_enc, lT, N_ROWS);
    norm_transpose_kernel<<<K_TOT / 32, 256>>>(g_enc, gT, K_TOT);
    contrastive_main_kernel<<<N_ROWS / 64, 256, smem_bytes>>>(out);
}

// round 3
// speedup vs baseline: 2.1060x; 2.1060x over previous
#include <cuda_runtime.h>
#include <cuda_bf16.h>
#include <cstdint>
#include <math.h>

// Problem dims (fixed): l_enc [1024,128,256] f32, g_enc [1024,256] f32.
#define N_ROWS 131072
#define K_TOT  1024
#define C_DIM  256
#define INV_T  5.0f

// Normalized bf16 operands (row-major, K-contiguous).
__device__ __nv_bfloat16 d_lbf[(size_t)N_ROWS * C_DIM];   // 64 MB
__device__ __nv_bfloat16 d_gbf[(size_t)K_TOT * C_DIM];    // 0.5 MB

// ---------------------------------------------------------------------------
// PTX helpers (sm_100 baseline ISA only: cp.async / ldmatrix / mma.sync)
// ---------------------------------------------------------------------------
__device__ __forceinline__ uint32_t smem_u32(const void* p) {
    uint32_t a;
    asm("{ .reg .u64 t; cvta.to.shared.u64 t, %1; cvt.u32.u64 %0, t; }"
        : "=r"(a) : "l"(p));
    return a;
}

#define CP_ASYNC16(dst, src) \
    asm volatile("cp.async.cg.shared.global [%0], [%1], 16;" \
                 :: "r"(dst), "l"(src) : "memory")
#define CP_COMMIT() asm volatile("cp.async.commit_group;" ::: "memory")
__device__ __forceinline__ void cp_wait1() {
    asm volatile("cp.async.wait_group 1;" ::: "memory");
}
__device__ __forceinline__ void cp_wait0() {
    asm volatile("cp.async.wait_group 0;" ::: "memory");
}

__device__ __forceinline__ void ldsm4(uint32_t* r, uint32_t addr) {
    asm volatile("ldmatrix.sync.aligned.m8n8.x4.shared.b16 {%0,%1,%2,%3}, [%4];"
                 : "=r"(r[0]), "=r"(r[1]), "=r"(r[2]), "=r"(r[3]) : "r"(addr));
}
__device__ __forceinline__ void ldsm2(uint32_t* r, uint32_t addr) {
    asm volatile("ldmatrix.sync.aligned.m8n8.x2.shared.b16 {%0,%1}, [%2];"
                 : "=r"(r[0]), "=r"(r[1]) : "r"(addr));
}

__device__ __forceinline__ void mma16816(float* d, const uint32_t* a,
                                         const uint32_t* b) {
    asm volatile(
        "mma.sync.aligned.m16n8k16.row.col.f32.bf16.bf16.f32 "
        "{%0,%1,%2,%3}, {%4,%5,%6,%7}, {%8,%9}, {%0,%1,%2,%3};"
        : "+f"(d[0]), "+f"(d[1]), "+f"(d[2]), "+f"(d[3])
        : "r"(a[0]), "r"(a[1]), "r"(a[2]), "r"(a[3]), "r"(b[0]), "r"(b[1]));
}

// ---------------------------------------------------------------------------
// Zero scalar output (d_out is poisoned by the harness).
// ---------------------------------------------------------------------------
__global__ void zero_out_kernel(float* out) {
    if (threadIdx.x == 0) out[0] = 0.0f;
}

// ---------------------------------------------------------------------------
// Normalize rows of [nrows,256] f32 -> bf16 row-major. 1 warp per row.
// ---------------------------------------------------------------------------
__global__ void norm_bf16_kernel(const float* __restrict__ src,
                                 __nv_bfloat16* __restrict__ dst) {
    const int row  = blockIdx.x * 8 + (threadIdx.x >> 5);
    const int lane = threadIdx.x & 31;
    const float4* s = (const float4*)(src + (size_t)row * C_DIM);
    const float4 v0 = s[lane * 2 + 0];
    const float4 v1 = s[lane * 2 + 1];
    float ss = v0.x*v0.x + v0.y*v0.y + v0.z*v0.z + v0.w*v0.w
             + v1.x*v1.x + v1.y*v1.y + v1.z*v1.z + v1.w*v1.w;
    #pragma unroll
    for (int o = 16; o > 0; o >>= 1) ss += __shfl_xor_sync(0xffffffffu, ss, o);
    const float rn = rsqrtf(ss);
    __nv_bfloat162* d = (__nv_bfloat162*)(dst + (size_t)row * C_DIM);
    d[lane * 4 + 0] = __floats2bfloat162_rn(v0.x * rn, v0.y * rn);
    d[lane * 4 + 1] = __floats2bfloat162_rn(v0.z * rn, v0.w * rn);
    d[lane * 4 + 2] = __floats2bfloat162_rn(v1.x * rn, v1.y * rn);
    d[lane * 4 + 3] = __floats2bfloat162_rn(v1.z * rn, v1.w * rn);
}

// ---------------------------------------------------------------------------
// Async tile load: 128 rows x 256 bf16 (512B/row) with XOR-16B swizzle.
// byte(row, c16) = row*512 + (c16>>3)*128 + (((c16 ^ row) & 7) << 4)
// ---------------------------------------------------------------------------
__device__ __forceinline__ void load_tile_async(uint32_t dst, const uint4* src,
                                                int tid) {
    #pragma unroll
    for (int i = 0; i < 16; i++) {
        const int idx = tid + i * 256;
        const int row = idx >> 5, c16 = idx & 31;
        const uint32_t off = (uint32_t)((row << 9) + ((c16 >> 3) << 7) +
                                        (((c16 ^ row) & 7) << 4));
        CP_ASYNC16(dst + off, src + (size_t)row * 32 + c16);
    }
}

// ---------------------------------------------------------------------------
// Main fused kernel: 1024 CTAs x 256 threads (8 warps: 4 m x 2 n).
// CTA bid owns l rows [bid*128, bid*128+128); their shared positive is g[bid].
// A (128x256) resident in smem; B tiles (128x256) double-buffered cp.async.
// acc in registers -> exp epilogue fused, no TMEM.
// ---------------------------------------------------------------------------
__global__ __launch_bounds__(256, 1)
void mma_main_kernel(float* __restrict__ out) {
    extern __shared__ __align__(1024) char smem[];
    char* smA = smem;                                   // 64 KB
    char* smB[2] = { smem + 65536, smem + 131072 };     // 2 x 64 KB

    __shared__ float sred[128][2];
    __shared__ float sposr[128][2];
    __shared__ float wsum[4];

    const int tid    = threadIdx.x;
    const int lane   = tid & 31;
    const int warp   = tid >> 5;
    const int warp_m = warp & 3;     // 4 m-warps: 32 rows each
    const int warp_n = warp >> 2;    // 2 n-warps: 64 cols each
    const int bid    = blockIdx.x;

    // ---- prologue: A + B0 (group 0), B1 (group 1) ----
    const uint32_t smA_u  = smem_u32(smA);
    const uint32_t smB_u[2] = { smem_u32(smB[0]), smem_u32(smB[1]) };
    const uint4* lg = (const uint4*)(d_lbf + (size_t)bid * 128 * C_DIM);
    const uint4* gg = (const uint4*)d_gbf;

    load_tile_async(smA_u, lg, tid);
    load_tile_async(smB_u[0], gg, tid);
    CP_COMMIT();
    load_tile_async(smB_u[1], gg + 128 * 32, tid);
    CP_COMMIT();

    // ldmatrix address bases
    const int a_row  = warp_m * 32 + (lane & 15);       // mt adds +16
    const int a_hi   = lane >> 4;
    const uint32_t axor   = (uint32_t)((a_row & 7) << 4);
    const uint32_t abase0 = smA_u + (a_row << 9);
    const uint32_t abase1 = abase0 + (16 << 9);
    const int b_row0 = warp_n * 64 + (lane & 7);        // nt adds +8
    const int b_hi   = (lane >> 3) & 1;
    const uint32_t bxor   = (uint32_t)((b_row0 & 7) << 4);

    const int ktb  = bid >> 7;       // B tile containing the positive column
    const int bcol = bid & 127;
    const bool cap_lane = (warp_n == (bcol >> 6)) && ((lane & 3) == ((bcol >> 1) & 3));
    const int cap_nt = (bcol >> 3) & 7;
    const int cap_j  = bcol & 1;

    float rs[2][2]  = {{0.f, 0.f}, {0.f, 0.f}};
    float pos[2][2] = {{0.f, 0.f}, {0.f, 0.f}};

    for (int kt = 0; kt < 8; kt++) {
        if (kt == 7) cp_wait0(); else cp_wait1();
        __syncthreads();
        const uint32_t bbase = smB_u[kt & 1] + (b_row0 << 9);

        float acc[2][8][4];
        #pragma unroll
        for (int mt = 0; mt < 2; mt++)
            #pragma unroll
            for (int nt = 0; nt < 8; nt++)
                #pragma unroll
                for (int j = 0; j < 4; j++) acc[mt][nt][j] = 0.0f;

        #pragma unroll
        for (int ks = 0; ks < 16; ks++) {
            const int kcA = 2 * ks + a_hi;
            const uint32_t aoff = (uint32_t)(((kcA >> 3) << 7) +
                                             ((((kcA & 7) << 4)) ^ axor));
            uint32_t a0[4], a1[4];
            ldsm4(a0, abase0 + aoff);
            ldsm4(a1, abase1 + aoff);
            const int kcB = 2 * ks + b_hi;
            const uint32_t boff = (uint32_t)(((kcB >> 3) << 7) +
                                             ((((kcB & 7) << 4)) ^ bxor));
            #pragma unroll
            for (int nt = 0; nt < 8; nt++) {
                uint32_t b[2];
                ldsm2(b, bbase + nt * 4096 + boff);
                mma16816(acc[0][nt], a0, b);
                mma16816(acc[1][nt], a1, b);
            }
        }

        // fused epilogue: exp-accumulate + positive capture
        #pragma unroll
        for (int mt = 0; mt < 2; mt++)
            #pragma unroll
            for (int nt = 0; nt < 8; nt++) {
                rs[mt][0] += __expf(acc[mt][nt][0] * INV_T)
                           + __expf(acc[mt][nt][1] * INV_T);
                rs[mt][1] += __expf(acc[mt][nt][2] * INV_T)
                           + __expf(acc[mt][nt][3] * INV_T);
            }
        if (kt == ktb && cap_lane) {
            pos[0][0] = acc[0][cap_nt][cap_j];
            pos[0][1] = acc[0][cap_nt][2 + cap_j];
            pos[1][0] = acc[1][cap_nt][cap_j];
            pos[1][1] = acc[1][cap_nt][2 + cap_j];
        }

        __syncthreads();
        if (kt + 2 < 8) {
            load_tile_async(smB_u[kt & 1], gg + (size_t)(kt + 2) * 128 * 32, tid);
            CP_COMMIT();
        }
    }

    // ---- per-row reduction: 4 lanes share a row -> shfl within quads ----
    #pragma unroll
    for (int mt = 0; mt < 2; mt++)
        #pragma unroll
        for (int h = 0; h < 2; h++) {
            float r = rs[mt][h];
            float p = pos[mt][h];
            r += __shfl_xor_sync(0xffffffffu, r, 1);
            r += __shfl_xor_sync(0xffffffffu, r, 2);
            p += __shfl_xor_sync(0xffffffffu, p, 1);
            p += __shfl_xor_sync(0xffffffffu, p, 2);
            if ((lane & 3) == 0) {
                const int row = warp_m * 32 + mt * 16 + h * 8 + (lane >> 2);
                sred[row][warp_n]  = r;
                sposr[row][warp_n] = p;
            }
        }
    __syncthreads();

    float v = 0.0f;
    if (tid < 128) {
        const float S = sred[tid][0] + sred[tid][1];
        const float p = (sposr[tid][0] + sposr[tid][1]) * INV_T;
        v = logf(S - __expf(p)) - p;
    }
    #pragma unroll
    for (int o = 16; o > 0; o >>= 1) v += __shfl_down_sync(0xffffffffu, v, o);
    if (tid < 128 && lane == 0) wsum[warp] = v;
    __syncthreads();
    if (tid == 0)
        atomicAdd(out, (wsum[0] + wsum[1] + wsum[2] + wsum[3]) *
                           (1.0f / (float)N_ROWS));
}

// ---------------------------------------------------------------------------
// Launch
// ---------------------------------------------------------------------------
extern "C" void kernel_launch(void* const* d_in, const int* in_sizes, int n_in,
                              void* d_out, int out_size) {
    const float* l_enc = (const float*)d_in[0];
    const float* g_enc = (const float*)d_in[1];
    float* out = (float*)d_out;

    __nv_bfloat16 *lbf = nullptr, *gbf = nullptr;
    cudaGetSymbolAddress((void**)&lbf, d_lbf);
    cudaGetSymbolAddress((void**)&gbf, d_gbf);

    const int smem_bytes = 3 * 65536;
    cudaFuncSetAttribute(mma_main_kernel,
                         cudaFuncAttributeMaxDynamicSharedMemorySize, smem_bytes);

    zero_out_kernel<<<1, 32>>>(out);
    norm_bf16_kernel<<<N_ROWS / 8, 256>>>(l_enc, lbf);
    norm_bf16_kernel<<<K_TOT / 8, 256>>>(g_enc, gbf);
    mma_main_kernel<<<K_TOT, 256, smem_bytes>>>(out);
}

// round 4
// speedup vs baseline: 10.2866x; 4.8844x over previous
#include <cuda_runtime.h>
#include <cuda_bf16.h>
#include <cstdint>
#include <math.h>

// Problem dims (fixed): l_enc [1024,128,256] f32, g_enc [1024,256] f32.
#define N_ROWS 131072
#define K_TOT  1024
#define C_DIM  256
#define INV_T  5.0f

// Normalized bf16 operands (row-major, K-contiguous).
__device__ __nv_bfloat16 d_lbf[(size_t)N_ROWS * C_DIM];   // 64 MB
__device__ __nv_bfloat16 d_gbf[(size_t)K_TOT * C_DIM];    // 0.5 MB

// ---------------------------------------------------------------------------
// PTX helpers (sm_100 baseline ISA: cp.async / ldmatrix / mma.sync)
// ---------------------------------------------------------------------------
__device__ __forceinline__ uint32_t smem_u32(const void* p) {
    uint32_t a;
    asm("{ .reg .u64 t; cvta.to.shared.u64 t, %1; cvt.u32.u64 %0, t; }"
        : "=r"(a) : "l"(p));
    return a;
}

#define CP_ASYNC16(dst, src) \
    asm volatile("cp.async.cg.shared.global [%0], [%1], 16;" \
                 :: "r"(dst), "l"(src) : "memory")
#define CP_COMMIT() asm volatile("cp.async.commit_group;" ::: "memory")
__device__ __forceinline__ void cp_wait1() {
    asm volatile("cp.async.wait_group 1;" ::: "memory");
}
__device__ __forceinline__ void cp_wait0() {
    asm volatile("cp.async.wait_group 0;" ::: "memory");
}

__device__ __forceinline__ void ldsm4(uint32_t* r, uint32_t addr) {
    asm volatile("ldmatrix.sync.aligned.m8n8.x4.shared.b16 {%0,%1,%2,%3}, [%4];"
                 : "=r"(r[0]), "=r"(r[1]), "=r"(r[2]), "=r"(r[3]) : "r"(addr));
}

__device__ __forceinline__ void mma16816(float* d, const uint32_t* a,
                                         const uint32_t* b) {
    asm volatile(
        "mma.sync.aligned.m16n8k16.row.col.f32.bf16.bf16.f32 "
        "{%0,%1,%2,%3}, {%4,%5,%6,%7}, {%8,%9}, {%0,%1,%2,%3};"
        : "+f"(d[0]), "+f"(d[1]), "+f"(d[2]), "+f"(d[3])
        : "r"(a[0]), "r"(a[1]), "r"(a[2]), "r"(a[3]), "r"(b[0]), "r"(b[1]));
}

// ---------------------------------------------------------------------------
__global__ void zero_out_kernel(float* out) {
    if (threadIdx.x == 0) out[0] = 0.0f;
}

// ---------------------------------------------------------------------------
// Normalize rows of [nrows,256] f32 -> bf16 row-major. 1 warp per row.
// ---------------------------------------------------------------------------
__global__ void norm_bf16_kernel(const float* __restrict__ src,
                                 __nv_bfloat16* __restrict__ dst) {
    const int row  = blockIdx.x * 8 + (threadIdx.x >> 5);
    const int lane = threadIdx.x & 31;
    const float4* s = (const float4*)(src + (size_t)row * C_DIM);
    const float4 v0 = s[lane * 2 + 0];
    const float4 v1 = s[lane * 2 + 1];
    float ss = v0.x*v0.x + v0.y*v0.y + v0.z*v0.z + v0.w*v0.w
             + v1.x*v1.x + v1.y*v1.y + v1.z*v1.z + v1.w*v1.w;
    #pragma unroll
    for (int o = 16; o > 0; o >>= 1) ss += __shfl_xor_sync(0xffffffffu, ss, o);
    const float rn = rsqrtf(ss);
    __nv_bfloat162* d = (__nv_bfloat162*)(dst + (size_t)row * C_DIM);
    d[lane * 4 + 0] = __floats2bfloat162_rn(v0.x * rn, v0.y * rn);
    d[lane * 4 + 1] = __floats2bfloat162_rn(v0.z * rn, v0.w * rn);
    d[lane * 4 + 2] = __floats2bfloat162_rn(v1.x * rn, v1.y * rn);
    d[lane * 4 + 3] = __floats2bfloat162_rn(v1.z * rn, v1.w * rn);
}

// ---------------------------------------------------------------------------
// Async tile load: 128 rows x 256 bf16 (512B/row) with XOR-16B swizzle.
// byte(row, c16) = row*512 + (c16>>3)*128 + (((c16 ^ row) & 7) << 4)
// ---------------------------------------------------------------------------
__device__ __forceinline__ void load_tile_async(uint32_t dst, const uint4* src,
                                                int tid) {
    #pragma unroll
    for (int i = 0; i < 8; i++) {
        const int idx = tid + i * 512;
        const int row = idx >> 5, c16 = idx & 31;
        const uint32_t off = (uint32_t)((row << 9) + ((c16 >> 3) << 7) +
                                        (((c16 ^ row) & 7) << 4));
        CP_ASYNC16(dst + off, src + (size_t)row * 32 + c16);
    }
}

// ---------------------------------------------------------------------------
// Main fused kernel: 1024 CTAs x 512 threads (16 warps: 4 m x 4 n).
// CTA bid owns l rows [bid*128, (bid+1)*128); shared positive is g[bid].
// Warp tile m32n32 (acc=32 regs). A resident; B double-buffered cp.async.
// ---------------------------------------------------------------------------
__global__ __launch_bounds__(512, 1)
void mma_main_kernel(float* __restrict__ out) {
    extern __shared__ __align__(1024) char smem[];
    char* smA = smem;                                   // 64 KB
    char* smB[2] = { smem + 65536, smem + 131072 };     // 2 x 64 KB

    __shared__ float sred[128][4];
    __shared__ float sposr[128][4];
    __shared__ float wsum[4];

    const int tid    = threadIdx.x;
    const int lane   = tid & 31;
    const int warp   = tid >> 5;
    const int warp_m = warp & 3;     // 4 m-warps: 32 rows each
    const int warp_n = warp >> 2;    // 4 n-warps: 32 cols each
    const int bid    = blockIdx.x;

    const uint32_t smA_u    = smem_u32(smA);
    const uint32_t smB_u[2] = { smem_u32(smB[0]), smem_u32(smB[1]) };
    const uint4* lg = (const uint4*)(d_lbf + (size_t)bid * 128 * C_DIM);
    const uint4* gg = (const uint4*)d_gbf;

    load_tile_async(smA_u, lg, tid);
    load_tile_async(smB_u[0], gg, tid);
    CP_COMMIT();
    load_tile_async(smB_u[1], gg + 128 * 32, tid);
    CP_COMMIT();

    // A ldmatrix.x4: lanes 0-15 -> 16 rows (k-half 0), lanes 16-31 same rows k-half 1
    const int a_row = warp_m * 32 + (lane & 15);
    const int a_hi  = lane >> 4;
    const uint32_t axor   = (uint32_t)((a_row & 7) << 4);
    const uint32_t abase0 = smA_u + (a_row << 9);
    const uint32_t abase1 = abase0 + (16 << 9);
    // B ldmatrix.x4: 16 n-rows per load: lanes 0-7 rows n0..7 kh0, 8-15 kh1,
    // 16-23 rows n0+8..15 kh0, 24-31 kh1 -> {r0,r1} frag nt, {r2,r3} frag nt+1
    const int b_row = warp_n * 32 + (lane & 7) + ((lane >> 4) << 3);
    const int b_hi  = (lane >> 3) & 1;
    const uint32_t bxor = (uint32_t)((b_row & 7) << 4);

    const int ktb  = bid >> 7;       // B tile containing the positive column
    const int bcol = bid & 127;
    const bool cap_lane = (warp_n == (bcol >> 5)) &&
                          ((lane & 3) == ((bcol >> 1) & 3));
    const int cap_nt = (bcol >> 3) & 3;
    const int cap_j  = bcol & 1;

    float rs[2][2]  = {{0.f, 0.f}, {0.f, 0.f}};
    float pos[2][2] = {{0.f, 0.f}, {0.f, 0.f}};

    for (int kt = 0; kt < 8; kt++) {
        if (kt == 7) cp_wait0(); else cp_wait1();
        __syncthreads();
        const uint32_t bbase = smB_u[kt & 1] + (b_row << 9);

        float acc[2][4][4];
        #pragma unroll
        for (int mt = 0; mt < 2; mt++)
            #pragma unroll
            for (int nt = 0; nt < 4; nt++)
                #pragma unroll
                for (int j = 0; j < 4; j++) acc[mt][nt][j] = 0.0f;

        #pragma unroll
        for (int ks = 0; ks < 16; ks++) {
            const int kcA = 2 * ks + a_hi;
            const uint32_t aoff = (uint32_t)(((kcA >> 3) << 7) +
                                             ((((kcA & 7) << 4)) ^ axor));
            uint32_t a0[4], a1[4];
            ldsm4(a0, abase0 + aoff);
            ldsm4(a1, abase1 + aoff);
            const int kcB = 2 * ks + b_hi;
            const uint32_t boff = (uint32_t)(((kcB >> 3) << 7) +
                                             ((((kcB & 7) << 4)) ^ bxor));
            #pragma unroll
            for (int pr = 0; pr < 2; pr++) {
                uint32_t b[4];
                ldsm4(b, bbase + pr * (16 << 9) + boff);
                mma16816(acc[0][2 * pr],     a0, b);
                mma16816(acc[0][2 * pr + 1], a0, b + 2);
                mma16816(acc[1][2 * pr],     a1, b);
                mma16816(acc[1][2 * pr + 1], a1, b + 2);
            }
        }

        // fused epilogue: exp-accumulate + positive capture
        #pragma unroll
        for (int mt = 0; mt < 2; mt++)
            #pragma unroll
            for (int nt = 0; nt < 4; nt++) {
                rs[mt][0] += __expf(acc[mt][nt][0] * INV_T)
                           + __expf(acc[mt][nt][1] * INV_T);
                rs[mt][1] += __expf(acc[mt][nt][2] * INV_T)
                           + __expf(acc[mt][nt][3] * INV_T);
            }
        if (kt == ktb && cap_lane) {
            pos[0][0] = acc[0][cap_nt][cap_j];
            pos[0][1] = acc[0][cap_nt][2 + cap_j];
            pos[1][0] = acc[1][cap_nt][cap_j];
            pos[1][1] = acc[1][cap_nt][2 + cap_j];
        }

        __syncthreads();
        if (kt + 2 < 8) {
            load_tile_async(smB_u[kt & 1], gg + (size_t)(kt + 2) * 128 * 32, tid);
            CP_COMMIT();
        }
    }

    // ---- per-row reduction: lane quads share a row ----
    #pragma unroll
    for (int mt = 0; mt < 2; mt++)
        #pragma unroll
        for (int h = 0; h < 2; h++) {
            float r = rs[mt][h];
            float p = pos[mt][h];
            r += __shfl_xor_sync(0xffffffffu, r, 1);
            r += __shfl_xor_sync(0xffffffffu, r, 2);
            p += __shfl_xor_sync(0xffffffffu, p, 1);
            p += __shfl_xor_sync(0xffffffffu, p, 2);
            if ((lane & 3) == 0) {
                const int row = warp_m * 32 + mt * 16 + h * 8 + (lane >> 2);
                sred[row][warp_n]  = r;
                sposr[row][warp_n] = p;
            }
        }
    __syncthreads();

    float v = 0.0f;
    if (tid < 128) {
        const float S = sred[tid][0] + sred[tid][1] + sred[tid][2] + sred[tid][3];
        const float p = (sposr[tid][0] + sposr[tid][1] +
                         sposr[tid][2] + sposr[tid][3]) * INV_T;
        v = logf(S - __expf(p)) - p;
    }
    #pragma unroll
    for (int o = 16; o > 0; o >>= 1) v += __shfl_down_sync(0xffffffffu, v, o);
    if (tid < 128 && lane == 0) wsum[warp] = v;
    __syncthreads();
    if (tid == 0)
        atomicAdd(out, (wsum[0] + wsum[1] + wsum[2] + wsum[3]) *
                           (1.0f / (float)N_ROWS));
}

// ---------------------------------------------------------------------------
extern "C" void kernel_launch(void* const* d_in, const int* in_sizes, int n_in,
                              void* d_out, int out_size) {
    const float* l_enc = (const float*)d_in[0];
    const float* g_enc = (const float*)d_in[1];
    float* out = (float*)d_out;

    __nv_bfloat16 *lbf = nullptr, *gbf = nullptr;
    cudaGetSymbolAddress((void**)&lbf, d_lbf);
    cudaGetSymbolAddress((void**)&gbf, d_gbf);

    const int smem_bytes = 3 * 65536;
    cudaFuncSetAttribute(mma_main_kernel,
                         cudaFuncAttributeMaxDynamicSharedMemorySize, smem_bytes);

    zero_out_kernel<<<1, 32>>>(out);
    norm_bf16_kernel<<<N_ROWS / 8, 256>>>(l_enc, lbf);
    norm_bf16_kernel<<<K_TOT / 8, 256>>>(g_enc, gbf);
    mma_main_kernel<<<K_TOT, 512, smem_bytes>>>(out);
}